// round 6
// baseline (speedup 1.0000x reference)
#include <cuda_runtime.h>
#include <math.h>
#include <stdint.h>

// Problem constants
#define BB 4
#define TT 4096
#define DD 1024
#define NC 512           // chunks along time
#define LL (TT / NC)     // 8 timesteps per chunk
#define ROW (3 * DD)

// Cross-block scan state (decoupled lookback)
__device__ float g_A[BB * NC * DD];   // chunk-local decay product
__device__ float g_S[BB * NC * DD];   // chunk-local offset
__device__ float g_H[BB * NC * DD];   // inclusive h at chunk end
__device__ int   g_flag[BB * NC];     // 0 = empty, 1 = local, 2 = inclusive

// ---- fast transcendentals (MUFU.TANH) -------------------------------------
__device__ __forceinline__ float tanh_fast(float v) {
    float r;
    asm("tanh.approx.f32 %0, %1;" : "=f"(r) : "f"(v));
    return r;
}
// sigmoid(v) = 0.5*tanh(0.5v) + 0.5

// ---- memory helpers --------------------------------------------------------
__device__ __forceinline__ float4 ldg_cs(const float* p) {   // read-once stream
    float4 v;
    asm("ld.global.nc.cs.v4.f32 {%0,%1,%2,%3}, [%4];"
        : "=f"(v.x), "=f"(v.y), "=f"(v.z), "=f"(v.w) : "l"(p));
    return v;
}
__device__ __forceinline__ void stg_cs(float* p, float4 v) {
    asm volatile("st.global.cs.v4.f32 [%0], {%1,%2,%3,%4};"
                 :: "l"(p), "f"(v.x), "f"(v.y), "f"(v.z), "f"(v.w));
}
__device__ __forceinline__ int ld_acq(const int* p) {
    int v;
    asm volatile("ld.global.acquire.gpu.b32 %0, [%1];" : "=r"(v) : "l"(p) : "memory");
    return v;
}
__device__ __forceinline__ void st_rel(int* p, int v) {
    asm volatile("st.global.release.gpu.b32 [%0], %1;" :: "l"(p), "r"(v) : "memory");
}

// ---------------------------------------------------------------------------
__global__ void k_reset() {
    int i = blockIdx.x * blockDim.x + threadIdx.x;
    if (i < BB * NC) g_flag[i] = 0;
}

// ---------------------------------------------------------------------------
// Fused kernel. Block (c, b): stream chunk -> summary -> publish local ->
// lookback -> publish inclusive -> replay from smem -> write y.
// Dynamic smem: [f | sv | og_s], each LL*DD floats (96 KB total).
// ---------------------------------------------------------------------------
__global__ __launch_bounds__(256, 2) void k_fused(const float* __restrict__ x,
                                                  const float* __restrict__ carry,
                                                  float* __restrict__ out) {
    extern __shared__ float sm[];
    float* sm_f  = sm;
    float* sm_sv = sm + LL * DD;
    float* sm_og = sm + 2 * LL * DD;
    __shared__ int s_n;
    __shared__ int s_v[8];

    const int c   = blockIdx.x;
    const int b   = blockIdx.y;
    const int tid = threadIdx.x;
    const int d   = tid * 4;

    const float* xb = x + (long)(b * TT + c * LL) * ROW + d;

    // -------- Phase 1: stream chunk, build smem planes + (A,S) summary -----
    float A[4] = {1.f, 1.f, 1.f, 1.f};
    float S[4] = {0.f, 0.f, 0.f, 0.f};

#pragma unroll
    for (int t = 0; t < LL; t++) {
        float4 ip4 = ldg_cs(xb + (long)t * ROW);
        float4 ig4 = ldg_cs(xb + (long)t * ROW + DD);
        float4 og4 = ldg_cs(xb + (long)t * ROW + 2 * DD);
        float ip[4] = {ip4.x, ip4.y, ip4.z, ip4.w};
        float ig[4] = {ig4.x, ig4.y, ig4.z, ig4.w};
        float og[4] = {og4.x, og4.y, og4.z, og4.w};
        float f[4], sv[4], os[4];
#pragma unroll
        for (int j = 0; j < 4; j++) {
            float tg  = tanh_fast(0.5f * ig[j]);
            float igs = fmaf(0.5f, tg, 0.5f);        // sigmoid(ig)
            f[j]      = fmaf(-0.5f, tg, 0.5f);       // 1 - sigmoid(ig)
            sv[j]     = tanh_fast(ip[j]) * igs;
            if (c == 0 && t == 0)
                sv[j] += carry[b * DD + d + j] * f[j];
            os[j]     = fmaf(0.5f, tanh_fast(0.5f * og[j]), 0.5f); // sigmoid(og)
            A[j] = f[j] * A[j];
            S[j] = fmaf(f[j], S[j], sv[j]);
        }
        *(float4*)(&sm_f [t * DD + d]) = make_float4(f[0],  f[1],  f[2],  f[3]);
        *(float4*)(&sm_sv[t * DD + d]) = make_float4(sv[0], sv[1], sv[2], sv[3]);
        *(float4*)(&sm_og[t * DD + d]) = make_float4(os[0], os[1], os[2], os[3]);
    }

    const int sidx = (b * NC + c) * DD + d;
    const int fidx = b * NC + c;

    // -------- Publish local summary (flag = 1) -----------------------------
    *(float4*)(&g_A[sidx]) = make_float4(A[0], A[1], A[2], A[3]);
    *(float4*)(&g_S[sidx]) = make_float4(S[0], S[1], S[2], S[3]);
    __syncthreads();
    if (tid == 0) {
        __threadfence();
        st_rel(&g_flag[fidx], 1);
    }

    // -------- Lookback: compose predecessors to get h_init -----------------
    float h_init[4] = {0.f, 0.f, 0.f, 0.f};
    if (c > 0) {
        float accA[4] = {1.f, 1.f, 1.f, 1.f};
        float accS[4] = {0.f, 0.f, 0.f, 0.f};
        int p = c - 1;
        bool done = false;
        while (!done) {
            if (tid == 0) {
                int v;
                do { v = ld_acq(&g_flag[b * NC + p]); } while (v == 0);
                s_v[0] = v;
                int n = 1;
                if (v == 1) {
                    while (n < 8 && p - n >= 0) {
                        int v2 = ld_acq(&g_flag[b * NC + p - n]);
                        if (v2 == 0) break;
                        s_v[n] = v2;
                        n++;
                        if (v2 == 2) break;
                    }
                }
                s_n = n;
            }
            __syncthreads();
            const int n = s_n;
            for (int i = 0; i < n; i++) {
                const int q = p - i;
                const int qidx = (b * NC + q) * DD + d;
                if (s_v[i] == 2) {
                    float4 H = *(const float4*)(&g_H[qidx]);
                    h_init[0] = fmaf(accA[0], H.x, accS[0]);
                    h_init[1] = fmaf(accA[1], H.y, accS[1]);
                    h_init[2] = fmaf(accA[2], H.z, accS[2]);
                    h_init[3] = fmaf(accA[3], H.w, accS[3]);
                    done = true;
                    break;
                } else {
                    float4 Aq = *(const float4*)(&g_A[qidx]);
                    float4 Sq = *(const float4*)(&g_S[qidx]);
                    accS[0] = fmaf(accA[0], Sq.x, accS[0]);
                    accS[1] = fmaf(accA[1], Sq.y, accS[1]);
                    accS[2] = fmaf(accA[2], Sq.z, accS[2]);
                    accS[3] = fmaf(accA[3], Sq.w, accS[3]);
                    accA[0] *= Aq.x; accA[1] *= Aq.y;
                    accA[2] *= Aq.z; accA[3] *= Aq.w;
                }
            }
            if (!done) {
                p -= n;
                if (p < 0) {   // reached the beginning: h before chunk 0 is 0
                    h_init[0] = accS[0]; h_init[1] = accS[1];
                    h_init[2] = accS[2]; h_init[3] = accS[3];
                    done = true;
                }
            }
            __syncthreads();   // protect s_v/s_n reuse
        }
    }

    // -------- Publish inclusive h_end (flag = 2) before replay -------------
    {
        float4 He = make_float4(fmaf(A[0], h_init[0], S[0]),
                                fmaf(A[1], h_init[1], S[1]),
                                fmaf(A[2], h_init[2], S[2]),
                                fmaf(A[3], h_init[3], S[3]));
        *(float4*)(&g_H[sidx]) = He;
    }
    __syncthreads();
    if (tid == 0) {
        __threadfence();
        st_rel(&g_flag[fidx], 2);
    }

    // -------- Phase 3: replay from smem, write y ---------------------------
    float* yb = out + (long)BB * DD + (long)(b * TT + c * LL) * DD + d;
    float h[4] = {h_init[0], h_init[1], h_init[2], h_init[3]};

#pragma unroll
    for (int t = 0; t < LL; t++) {
        float4 f4  = *(const float4*)(&sm_f [t * DD + d]);
        float4 sv4 = *(const float4*)(&sm_sv[t * DD + d]);
        float4 og4 = *(const float4*)(&sm_og[t * DD + d]);
        h[0] = fmaf(f4.x, h[0], sv4.x);
        h[1] = fmaf(f4.y, h[1], sv4.y);
        h[2] = fmaf(f4.z, h[2], sv4.z);
        h[3] = fmaf(f4.w, h[3], sv4.w);
        float4 y4 = make_float4(tanh_fast(h[0]) * og4.x,
                                tanh_fast(h[1]) * og4.y,
                                tanh_fast(h[2]) * og4.z,
                                tanh_fast(h[3]) * og4.w);
        stg_cs(yb + (long)t * DD, y4);
    }

    // h_last from the final chunk
    if (c == NC - 1)
        *(float4*)(out + b * DD + d) = make_float4(h[0], h[1], h[2], h[3]);
}

extern "C" void kernel_launch(void* const* d_in, const int* in_sizes, int n_in,
                              void* d_out, int out_size) {
    const float* x     = (const float*)d_in[0];
    const float* carry = (const float*)d_in[1];
    float* out         = (float*)d_out;

    const int smem_bytes = 3 * LL * DD * sizeof(float);   // 96 KB
    cudaFuncSetAttribute(k_fused, cudaFuncAttributeMaxDynamicSharedMemorySize,
                         smem_bytes);

    k_reset<<<(BB * NC + 1023) / 1024, 1024>>>();
    dim3 grid(NC, BB);   // c fastest: predecessors always have lower linear bid
    k_fused<<<grid, 256, smem_bytes>>>(x, carry, out);
}